// round 9
// baseline (speedup 1.0000x reference)
#include <cuda_runtime.h>
#include <cuda_bf16.h>
#include <cstdint>

#define BB 1024
#define TT 512
#define HH 256
#define NTHR 512
#define WSTRIDE 264          // bf16 elems per SMEM row (K=256 + 8 pad) -> 528 B
#define WHI_OFF 0            // 128*528 = 67584
#define WLO_OFF 67584
#define HHI_OFF 135168       // 64*528 = 33792
#define HLO_OFF 168960
#define WI_OFF  202752       // 128 floats
#define BIAS_OFF 203264      // 128 floats
#define XS_OFF  203776       // 64 rows x 34 floats = 8704 B
#define SMEM_TOTAL 212480

__device__ __nv_bfloat16 g_hhi[BB * HH];
__device__ __nv_bfloat16 g_hlo[BB * HH];

__device__ __forceinline__ void ldsm4(uint32_t a, uint32_t &r0, uint32_t &r1, uint32_t &r2, uint32_t &r3) {
    asm volatile("ldmatrix.sync.aligned.m8n8.x4.shared.b16 {%0,%1,%2,%3},[%4];"
                 : "=r"(r0), "=r"(r1), "=r"(r2), "=r"(r3) : "r"(a));
}
__device__ __forceinline__ void mma_bf16(float *c, uint32_t a0, uint32_t a1, uint32_t a2, uint32_t a3,
                                         uint32_t b0, uint32_t b1) {
    asm volatile("mma.sync.aligned.m16n8k16.row.col.f32.bf16.bf16.f32 "
                 "{%0,%1,%2,%3},{%4,%5,%6,%7},{%8,%9},{%0,%1,%2,%3};"
                 : "+f"(c[0]), "+f"(c[1]), "+f"(c[2]), "+f"(c[3])
                 : "r"(a0), "r"(a1), "r"(a2), "r"(a3), "r"(b0), "r"(b1));
}
__device__ __forceinline__ void cpasync16(uint32_t dst, const void *src) {
    asm volatile("cp.async.cg.shared.global [%0],[%1],16;" :: "r"(dst), "l"(src));
}
__device__ __forceinline__ float fsigmoid(float x) { return __fdividef(1.0f, 1.0f + __expf(-x)); }
__device__ __forceinline__ float ftanh(float x) {
    float e = __expf(2.0f * x);
    return 1.0f - __fdividef(2.0f, e + 1.0f);
}

extern __shared__ char smem_raw[];

__global__ void __launch_bounds__(NTHR, 1) __cluster_dims__(8, 1, 1)
lstm_kernel(const float *__restrict__ x, const float *__restrict__ W_ih,
            const float *__restrict__ W_hh, const float *__restrict__ b_ih,
            const float *__restrict__ b_hh, const float *__restrict__ W_lin,
            const float *__restrict__ b_lin, float *__restrict__ out) {
    __nv_bfloat16 *WHI = (__nv_bfloat16 *)(smem_raw + WHI_OFF);
    __nv_bfloat16 *WLO = (__nv_bfloat16 *)(smem_raw + WLO_OFF);
    float *WI    = (float *)(smem_raw + WI_OFF);
    float *BIASS = (float *)(smem_raw + BIAS_OFF);
    float *XS    = (float *)(smem_raw + XS_OFF);

    const int tid  = threadIdx.x;
    const int grp  = blockIdx.x >> 3;   // batch group 0..15 (64 rows) == cluster id
    const int sl   = blockIdx.x & 7;    // hidden slice 0..7 (32 units) == cluster rank
    const int lane = tid & 31;
    const int warp = tid >> 5;          // 0..15
    const int wm   = warp >> 2, wn = warp & 3;   // 4 x 4 warp grid

    // ---- one-time: W_hh slice, unit-interleaved rows j = 4*unit + gate ----
    for (int it = tid; it < 128 * 64; it += NTHR) {
        int j = it >> 6, c4 = it & 63;
        int r = ((j & 3) << 8) + (sl << 5) + (j >> 2);
        float4 v = __ldg((const float4 *)(W_hh + r * HH) + c4);
        float f[4] = {v.x, v.y, v.z, v.w};
        __nv_bfloat16 hi[4], lo[4];
#pragma unroll
        for (int e = 0; e < 4; e++) {
            hi[e] = __float2bfloat16(f[e]);
            lo[e] = __float2bfloat16(f[e] - __bfloat162float(hi[e]));
        }
        __nv_bfloat162 *dh = (__nv_bfloat162 *)(WHI + j * WSTRIDE + c4 * 4);
        __nv_bfloat162 *dl = (__nv_bfloat162 *)(WLO + j * WSTRIDE + c4 * 4);
        dh[0] = __halves2bfloat162(hi[0], hi[1]);
        dh[1] = __halves2bfloat162(hi[2], hi[3]);
        dl[0] = __halves2bfloat162(lo[0], lo[1]);
        dl[1] = __halves2bfloat162(lo[2], lo[3]);
    }
    if (tid < 128) {
        int r = ((tid & 3) << 8) + (sl << 5) + (tid >> 2);
        WI[tid]    = W_ih[r];
        BIASS[tid] = b_ih[r] + b_hh[r];
    }
    __syncthreads();

    const int m0 = wm * 16;   // 16-row warp tile
    const uint32_t hhi_u = (uint32_t)__cvta_generic_to_shared(smem_raw + HHI_OFF);
    const uint32_t hlo_u = (uint32_t)__cvta_generic_to_shared(smem_raw + HLO_OFF);
    const uint32_t whi_u = (uint32_t)__cvta_generic_to_shared(WHI);
    const uint32_t wlo_u = (uint32_t)__cvta_generic_to_shared(WLO);
    // A m16k16 fragment: lanes 0-15 rows m0..15 @k0, lanes 16-31 same rows @k8
    const uint32_t aOff = (uint32_t)((m0 + (lane & 15)) * 528 + ((lane >> 4) * 8) * 2);
    // B j-pair x4: lanes 0-7 (j0,k0), 8-15 (j0,k8), 16-23 (j1,k0), 24-31 (j1,k8)
    const uint32_t bP0 = (uint32_t)((wn * 32 + (lane >> 4) * 8 + (lane & 7)) * 528 +
                                    ((lane >> 3) & 1) * 16);
    const uint32_t bP1 = bP0 + 16 * 528;

    // epilogue mapping (lane-pair exchange): thread owns row rloc, 4 units
    const int p = lane & 1, q = lane >> 2;
    const int rloc = m0 + q + 8 * p;
    int hcol[4];
#pragma unroll
    for (int j = 0; j < 4; j++) hcol[j] = sl * 32 + wn * 8 + 2 * j + ((lane & 3) >> 1);

    float creg[4];
#pragma unroll
    for (int j = 0; j < 4; j++) creg[j] = 0.0f;

    const __nv_bfloat16 *shi = g_hhi + grp * 64 * HH;
    const __nv_bfloat16 *slo = g_hlo + grp * 64 * HH;

    // ensure W/bias staging of all cluster CTAs done before first step's stores race anything
    asm volatile("barrier.cluster.arrive.aligned;" ::: "memory");
    asm volatile("barrier.cluster.wait.aligned;" ::: "memory");

    for (int t = 0; t < TT; ++t) {
        // ---- comm-in: h tile via cp.async; x tile (every 32 steps) via LDG+STS ----
        if (t > 0) {
#pragma unroll
            for (int k = 0; k < 4; ++k) {
                int g = k * NTHR + tid;   // 2048 16B chunks per array
                uint32_t off = (uint32_t)((g >> 5) * 528 + (g & 31) * 16);
                cpasync16(hhi_u + off, shi + g * 8);
                cpasync16(hlo_u + off, slo + g * 8);
            }
            asm volatile("cp.async.commit_group;");
        }
        if ((t & 31) == 0) {
            // 64 rows x 8 float4 chunks = 512; one per thread. 136B stride -> scalar STS.
            int row = tid >> 3, c = tid & 7;
            float4 v = __ldg((const float4 *)(x + (grp * 64 + row) * TT + t) + c);
            float *dst = &XS[row * 34 + c * 4];
            dst[0] = v.x; dst[1] = v.y; dst[2] = v.z; dst[3] = v.w;
        }
        if (t > 0) asm volatile("cp.async.wait_group 0;");
        __syncthreads();   // h tile + x tile visible CTA-wide

        float acc[4][4];
#pragma unroll
        for (int j = 0; j < 4; j++)
#pragma unroll
            for (int e = 0; e < 4; e++) acc[j][e] = 0.0f;

        if (t > 0) {
#pragma unroll
            for (int kk = 0; kk < 16; ++kk) {
                const uint32_t kB = (uint32_t)(kk * 32);
                uint32_t ah[4], al[4], bh[4][2], bl[4][2];
                ldsm4(hhi_u + aOff + kB, ah[0], ah[1], ah[2], ah[3]);
                ldsm4(hlo_u + aOff + kB, al[0], al[1], al[2], al[3]);
                ldsm4(whi_u + bP0 + kB, bh[0][0], bh[0][1], bh[1][0], bh[1][1]);
                ldsm4(whi_u + bP1 + kB, bh[2][0], bh[2][1], bh[3][0], bh[3][1]);
                ldsm4(wlo_u + bP0 + kB, bl[0][0], bl[0][1], bl[1][0], bl[1][1]);
                ldsm4(wlo_u + bP1 + kB, bl[2][0], bl[2][1], bl[3][0], bl[3][1]);
#pragma unroll
                for (int j = 0; j < 4; j++) {
                    mma_bf16(acc[j], ah[0], ah[1], ah[2], ah[3], bh[j][0], bh[j][1]);
                    mma_bf16(acc[j], ah[0], ah[1], ah[2], ah[3], bl[j][0], bl[j][1]);
                    mma_bf16(acc[j], al[0], al[1], al[2], al[3], bh[j][0], bh[j][1]);
                }
            }
        }

        // ---- in-register epilogue ----
        {
            const int ts = t & 31;
            const int grow = grp * 64 + rloc;
            const float xv = XS[rloc * 34 + ts];
#pragma unroll
            for (int j = 0; j < 4; j++) {
                float a0 = acc[j][0], a1 = acc[j][1], a2 = acc[j][2], a3 = acc[j][3];
                float s1 = p ? a0 : a2;
                float r1 = __shfl_xor_sync(0xFFFFFFFFu, s1, 1);
                float s2 = p ? a1 : a3;
                float r2 = __shfl_xor_sync(0xFFFFFFFFu, s2, 1);
                float gi = p ? r1 : a0;
                float gf = p ? r2 : a1;
                float gg = p ? a2 : r1;
                float go = p ? a3 : r2;
                int u4 = (hcol[j] - sl * 32) * 4;
                float4 wi4 = *(const float4 *)&WI[u4];
                float4 bi4 = *(const float4 *)&BIASS[u4];
                gi += xv * wi4.x + bi4.x;
                gf += xv * wi4.y + bi4.y;
                gg += xv * wi4.z + bi4.z;
                go += xv * wi4.w + bi4.w;
                float cc = fsigmoid(gf) * creg[j] + fsigmoid(gi) * ftanh(gg);
                creg[j] = cc;
                float h = fsigmoid(go) * ftanh(cc);
                __nv_bfloat16 hh = __float2bfloat16(h);
                __nv_bfloat16 hl = __float2bfloat16(h - __bfloat162float(hh));
                int gidx = grow * HH + hcol[j];
                g_hhi[gidx] = hh;
                g_hlo[gidx] = hl;
            }
        }

        // ---- HW cluster barrier: release h stores, sync the 8-CTA group ----
        asm volatile("barrier.cluster.arrive.aligned;" ::: "memory");
        asm volatile("barrier.cluster.wait.aligned;" ::: "memory");
    }

    // ---- fused final projection: warps 0-7 output rows grp*64 + sl*8 + warp ----
    if (warp < 8) {
        int b = grp * 64 + sl * 8 + warp;
        const __nv_bfloat16 *hh = g_hhi + b * HH;
        const __nv_bfloat16 *hl = g_hlo + b * HH;
        float s = 0.0f;
#pragma unroll
        for (int k = lane; k < HH; k += 32) {
            float hv = __bfloat162float(__ldcg(&hh[k])) + __bfloat162float(__ldcg(&hl[k]));
            s += hv * __ldg(&W_lin[k]);
        }
#pragma unroll
        for (int o = 16; o > 0; o >>= 1) s += __shfl_xor_sync(0xFFFFFFFFu, s, o);
        if (lane == 0) out[b] = s + __ldg(&b_lin[0]);
    }
}

extern "C" void kernel_launch(void *const *d_in, const int *in_sizes, int n_in,
                              void *d_out, int out_size) {
    (void)in_sizes; (void)n_in; (void)out_size;
    const float *x     = (const float *)d_in[0];
    const float *W_ih  = (const float *)d_in[1];
    const float *W_hh  = (const float *)d_in[2];
    const float *b_ih  = (const float *)d_in[3];
    const float *b_hh  = (const float *)d_in[4];
    const float *W_lin = (const float *)d_in[5];
    const float *b_lin = (const float *)d_in[6];
    float *out = (float *)d_out;

    static bool attr_set = false;
    if (!attr_set) {
        cudaFuncSetAttribute(lstm_kernel, cudaFuncAttributeMaxDynamicSharedMemorySize, SMEM_TOTAL);
        attr_set = true;
    }
    lstm_kernel<<<128, NTHR, SMEM_TOTAL>>>(x, W_ih, W_hh, b_ih, b_hh, W_lin, b_lin, out);
}

// round 10
// speedup vs baseline: 2.2805x; 2.2805x over previous
#include <cuda_runtime.h>
#include <cuda_fp16.h>
#include <cstdint>

#define BB 1024
#define TT 512
#define HH 256
#define NTHR 512
#define WSTRIDE 264          // fp16 elems per SMEM row (K=256 + 8 pad) -> 528 B
#define WHI_OFF 0            // 128*528 = 67584
#define HHI_OFF 67584        // 64*528 = 33792
#define HLO_OFF 101376
#define WI_OFF  135168       // 128 floats
#define BIAS_OFF 135680      // 128 floats
#define XS_OFF  136192       // 64 rows x 34 floats = 8704 B
#define SMEM_TOTAL 145408

__device__ __half g_hhi[BB * HH];
__device__ __half g_hlo[BB * HH];
__device__ unsigned g_bar[16][512];   // zero at load; self-cleaning ring

__device__ __forceinline__ void ldsm4(uint32_t a, uint32_t &r0, uint32_t &r1, uint32_t &r2, uint32_t &r3) {
    asm volatile("ldmatrix.sync.aligned.m8n8.x4.shared.b16 {%0,%1,%2,%3},[%4];"
                 : "=r"(r0), "=r"(r1), "=r"(r2), "=r"(r3) : "r"(a));
}
__device__ __forceinline__ void mma_f16(float *c, uint32_t a0, uint32_t a1, uint32_t a2, uint32_t a3,
                                        uint32_t b0, uint32_t b1) {
    asm volatile("mma.sync.aligned.m16n8k16.row.col.f32.f16.f16.f32 "
                 "{%0,%1,%2,%3},{%4,%5,%6,%7},{%8,%9},{%0,%1,%2,%3};"
                 : "+f"(c[0]), "+f"(c[1]), "+f"(c[2]), "+f"(c[3])
                 : "r"(a0), "r"(a1), "r"(a2), "r"(a3), "r"(b0), "r"(b1));
}
__device__ __forceinline__ void cpasync16(uint32_t dst, const void *src) {
    asm volatile("cp.async.cg.shared.global [%0],[%1],16;" :: "r"(dst), "l"(src));
}
__device__ __forceinline__ float fsigmoid(float x) { return __fdividef(1.0f, 1.0f + __expf(-x)); }
__device__ __forceinline__ float ftanh(float x) {
    float e = __expf(2.0f * x);
    return 1.0f - __fdividef(2.0f, e + 1.0f);
}

extern __shared__ char smem_raw[];

__global__ void __launch_bounds__(NTHR, 1)
lstm_kernel(const float *__restrict__ x, const float *__restrict__ W_ih,
            const float *__restrict__ W_hh, const float *__restrict__ b_ih,
            const float *__restrict__ b_hh, const float *__restrict__ W_lin,
            const float *__restrict__ b_lin, float *__restrict__ out) {
    __half *WHI  = (__half *)(smem_raw + WHI_OFF);
    float *WI    = (float *)(smem_raw + WI_OFF);
    float *BIASS = (float *)(smem_raw + BIAS_OFF);
    float *XS    = (float *)(smem_raw + XS_OFF);

    const int tid  = threadIdx.x;
    const int grp  = blockIdx.x >> 3;   // batch group 0..15 (64 rows)
    const int sl   = blockIdx.x & 7;    // hidden slice 0..7 (32 units)
    const int lane = tid & 31;
    const int warp = tid >> 5;          // 0..15
    const int wm   = warp >> 2, wn = warp & 3;   // 4 x 4 warp grid

    // ---- one-time: W_hh slice (single fp16), unit-interleaved rows j = 4*unit + gate ----
    for (int it = tid; it < 128 * 64; it += NTHR) {
        int j = it >> 6, c4 = it & 63;
        int r = ((j & 3) << 8) + (sl << 5) + (j >> 2);
        float4 v = __ldg((const float4 *)(W_hh + r * HH) + c4);
        __half2 *dh = (__half2 *)(WHI + j * WSTRIDE + c4 * 4);
        dh[0] = __halves2half2(__float2half_rn(v.x), __float2half_rn(v.y));
        dh[1] = __halves2half2(__float2half_rn(v.z), __float2half_rn(v.w));
    }
    if (tid < 128) {
        int r = ((tid & 3) << 8) + (sl << 5) + (tid >> 2);
        WI[tid]    = W_ih[r];
        BIASS[tid] = b_ih[r] + b_hh[r];
    }
    __syncthreads();

    const int m0 = wm * 16;   // 16-row warp tile
    const uint32_t hhi_u = (uint32_t)__cvta_generic_to_shared(smem_raw + HHI_OFF);
    const uint32_t hlo_u = (uint32_t)__cvta_generic_to_shared(smem_raw + HLO_OFF);
    const uint32_t whi_u = (uint32_t)__cvta_generic_to_shared(WHI);
    // A m16k16 fragment: lanes 0-15 rows m0..15 @k0, lanes 16-31 same rows @k8
    const uint32_t aOff = (uint32_t)((m0 + (lane & 15)) * 528 + ((lane >> 4) * 8) * 2);
    // B j-pair x4: lanes 0-7 (j0,k0), 8-15 (j0,k8), 16-23 (j1,k0), 24-31 (j1,k8)
    const uint32_t bP0 = (uint32_t)((wn * 32 + (lane >> 4) * 8 + (lane & 7)) * 528 +
                                    ((lane >> 3) & 1) * 16);
    const uint32_t bP1 = bP0 + 16 * 528;

    // epilogue mapping (lane-pair exchange): thread owns row rloc, 4 units
    const int p = lane & 1, q = lane >> 2;
    const int rloc = m0 + q + 8 * p;
    int hcol[4];
#pragma unroll
    for (int j = 0; j < 4; j++) hcol[j] = sl * 32 + wn * 8 + 2 * j + ((lane & 3) >> 1);

    float creg[4];
#pragma unroll
    for (int j = 0; j < 4; j++) creg[j] = 0.0f;

    unsigned *barg = g_bar[grp];
    const __half *shi = g_hhi + grp * 64 * HH;
    const __half *slo = g_hlo + grp * 64 * HH;

    for (int t = 0; t < TT; ++t) {
        // ---- comm-in: h tile via cp.async; x tile (every 32 steps) via LDG+STS ----
        if (t > 0) {
#pragma unroll
            for (int k = 0; k < 4; ++k) {
                int g = k * NTHR + tid;   // 2048 16B chunks per array
                uint32_t off = (uint32_t)((g >> 5) * 528 + (g & 31) * 16);
                cpasync16(hhi_u + off, shi + g * 8);
                cpasync16(hlo_u + off, slo + g * 8);
            }
            asm volatile("cp.async.commit_group;");
        }
        if ((t & 31) == 0) {
            // 64 rows x 8 float4 chunks = 512; one per thread. 136B stride -> scalar STS.
            int row = tid >> 3, c = tid & 7;
            float4 v = __ldg((const float4 *)(x + (grp * 64 + row) * TT + t) + c);
            float *dst = &XS[row * 34 + c * 4];
            dst[0] = v.x; dst[1] = v.y; dst[2] = v.z; dst[3] = v.w;
        }
        if (t > 0) asm volatile("cp.async.wait_group 0;");
        __syncthreads();   // h tile + x tile visible CTA-wide

        float acc[4][4];
#pragma unroll
        for (int j = 0; j < 4; j++)
#pragma unroll
            for (int e = 0; e < 4; e++) acc[j][e] = 0.0f;

        if (t > 0) {
#pragma unroll
            for (int kk = 0; kk < 16; ++kk) {
                const uint32_t kB = (uint32_t)(kk * 32);
                uint32_t ah[4], al[4], bh[4][2];
                ldsm4(hhi_u + aOff + kB, ah[0], ah[1], ah[2], ah[3]);
                ldsm4(hlo_u + aOff + kB, al[0], al[1], al[2], al[3]);
                ldsm4(whi_u + bP0 + kB, bh[0][0], bh[0][1], bh[1][0], bh[1][1]);
                ldsm4(whi_u + bP1 + kB, bh[2][0], bh[2][1], bh[3][0], bh[3][1]);
#pragma unroll
                for (int j = 0; j < 4; j++) {
                    mma_f16(acc[j], ah[0], ah[1], ah[2], ah[3], bh[j][0], bh[j][1]);
                    mma_f16(acc[j], al[0], al[1], al[2], al[3], bh[j][0], bh[j][1]);
                }
            }
        }

        // ---- in-register epilogue ----
        {
            const int ts = t & 31;
            const int grow = grp * 64 + rloc;
            const float xv = XS[rloc * 34 + ts];
#pragma unroll
            for (int j = 0; j < 4; j++) {
                float a0 = acc[j][0], a1 = acc[j][1], a2 = acc[j][2], a3 = acc[j][3];
                float s1 = p ? a0 : a2;
                float r1 = __shfl_xor_sync(0xFFFFFFFFu, s1, 1);
                float s2 = p ? a1 : a3;
                float r2 = __shfl_xor_sync(0xFFFFFFFFu, s2, 1);
                float gi = p ? r1 : a0;
                float gf = p ? r2 : a1;
                float gg = p ? a2 : r1;
                float go = p ? a3 : r2;
                int u4 = (hcol[j] - sl * 32) * 4;
                float4 wi4 = *(const float4 *)&WI[u4];
                float4 bi4 = *(const float4 *)&BIASS[u4];
                gi += xv * wi4.x + bi4.x;
                gf += xv * wi4.y + bi4.y;
                gg += xv * wi4.z + bi4.z;
                go += xv * wi4.w + bi4.w;
                float cc = fsigmoid(gf) * creg[j] + fsigmoid(gi) * ftanh(gg);
                creg[j] = cc;
                float h = fsigmoid(go) * ftanh(cc);
                __half hh = __float2half_rn(h);
                __half hl = __float2half_rn(h - __half2float(hh));
                int gidx = grow * HH + hcol[j];
                g_hhi[gidx] = hh;
                g_hlo[gidx] = hl;
            }
        }

        // ---- group barrier: tid0 arrive (release), ALL warps acquire-poll ----
        __syncthreads();   // all h-stores of this CTA done before release
        if (tid == 0) {
            if (sl == 0) {
                unsigned *rst = &barg[(t + 448) & 511];
                asm volatile("st.relaxed.gpu.global.u32 [%0],%1;" :: "l"(rst), "r"(0u) : "memory");
            }
            asm volatile("red.release.gpu.global.add.u32 [%0],%1;" :: "l"(&barg[t]), "r"(1u) : "memory");
        }
        if (lane == 0) {
            unsigned v;
            do {
                asm volatile("ld.acquire.gpu.u32 %0,[%1];" : "=r"(v) : "l"(&barg[t]) : "memory");
            } while (v < 8u);
        }
        __syncwarp();
    }

    // ---- fused final projection: warps 0-7 output rows grp*64 + sl*8 + warp ----
    if (warp < 8) {
        int b = grp * 64 + sl * 8 + warp;
        const __half *hh = g_hhi + b * HH;
        const __half *hl = g_hlo + b * HH;
        float s = 0.0f;
#pragma unroll
        for (int k = lane; k < HH; k += 32) {
            float hv = __half2float(__ldcg(&hh[k])) + __half2float(__ldcg(&hl[k]));
            s += hv * __ldg(&W_lin[k]);
        }
#pragma unroll
        for (int o = 16; o > 0; o >>= 1) s += __shfl_xor_sync(0xFFFFFFFFu, s, o);
        if (lane == 0) out[b] = s + __ldg(&b_lin[0]);
    }
}

extern "C" void kernel_launch(void *const *d_in, const int *in_sizes, int n_in,
                              void *d_out, int out_size) {
    (void)in_sizes; (void)n_in; (void)out_size;
    const float *x     = (const float *)d_in[0];
    const float *W_ih  = (const float *)d_in[1];
    const float *W_hh  = (const float *)d_in[2];
    const float *b_ih  = (const float *)d_in[3];
    const float *b_hh  = (const float *)d_in[4];
    const float *W_lin = (const float *)d_in[5];
    const float *b_lin = (const float *)d_in[6];
    float *out = (float *)d_out;

    static bool attr_set = false;
    if (!attr_set) {
        cudaFuncSetAttribute(lstm_kernel, cudaFuncAttributeMaxDynamicSharedMemorySize, SMEM_TOTAL);
        attr_set = true;
    }
    lstm_kernel<<<128, NTHR, SMEM_TOTAL>>>(x, W_ih, W_hh, b_ih, b_hh, W_lin, b_lin, out);
}

// round 11
// speedup vs baseline: 3.0740x; 1.3480x over previous
#include <cuda_runtime.h>
#include <cuda_fp16.h>
#include <cstdint>

#define BB 1024
#define TT 512
#define HH 256
#define NTHR 512
#define WSTRIDE 264          // fp16 elems per SMEM row (K=256 + 8 pad) -> 528 B
#define WHI_OFF 0            // 128*528 = 67584
#define HHI_OFF 67584        // 64*528 = 33792
#define WI_OFF  101376       // 128 floats
#define BIAS_OFF 101888      // 128 floats
#define XS_OFF  102400       // 64 rows x 34 floats = 8704 B
#define SMEM_TOTAL 111616

__device__ __half g_hh[BB * HH];
__device__ unsigned g_bar[16][512];   // zero at load; self-cleaning ring

__device__ __forceinline__ void ldsm4(uint32_t a, uint32_t &r0, uint32_t &r1, uint32_t &r2, uint32_t &r3) {
    asm volatile("ldmatrix.sync.aligned.m8n8.x4.shared.b16 {%0,%1,%2,%3},[%4];"
                 : "=r"(r0), "=r"(r1), "=r"(r2), "=r"(r3) : "r"(a));
}
__device__ __forceinline__ void mma_f16(float *c, uint32_t a0, uint32_t a1, uint32_t a2, uint32_t a3,
                                        uint32_t b0, uint32_t b1) {
    asm volatile("mma.sync.aligned.m16n8k16.row.col.f32.f16.f16.f32 "
                 "{%0,%1,%2,%3},{%4,%5,%6,%7},{%8,%9},{%0,%1,%2,%3};"
                 : "+f"(c[0]), "+f"(c[1]), "+f"(c[2]), "+f"(c[3])
                 : "r"(a0), "r"(a1), "r"(a2), "r"(a3), "r"(b0), "r"(b1));
}
__device__ __forceinline__ void cpasync16(uint32_t dst, const void *src) {
    asm volatile("cp.async.cg.shared.global [%0],[%1],16;" :: "r"(dst), "l"(src));
}
__device__ __forceinline__ float fsigmoid(float x) { return __fdividef(1.0f, 1.0f + __expf(-x)); }
__device__ __forceinline__ float ftanh(float x) {
    float e = __expf(2.0f * x);
    return 1.0f - __fdividef(2.0f, e + 1.0f);
}

extern __shared__ char smem_raw[];

__global__ void __launch_bounds__(NTHR, 1)
lstm_kernel(const float *__restrict__ x, const float *__restrict__ W_ih,
            const float *__restrict__ W_hh, const float *__restrict__ b_ih,
            const float *__restrict__ b_hh, const float *__restrict__ W_lin,
            const float *__restrict__ b_lin, float *__restrict__ out) {
    __half *WHI  = (__half *)(smem_raw + WHI_OFF);
    float *WI    = (float *)(smem_raw + WI_OFF);
    float *BIASS = (float *)(smem_raw + BIAS_OFF);
    float *XS    = (float *)(smem_raw + XS_OFF);

    const int tid  = threadIdx.x;
    const int grp  = blockIdx.x >> 3;   // batch group 0..15 (64 rows)
    const int sl   = blockIdx.x & 7;    // hidden slice 0..7 (32 units)
    const int lane = tid & 31;
    const int warp = tid >> 5;          // 0..15
    const int wm   = warp >> 2, wn = warp & 3;   // 4 x 4 warp grid

    // ---- one-time: W_hh slice (single fp16), unit-interleaved rows j = 4*unit + gate ----
    for (int it = tid; it < 128 * 64; it += NTHR) {
        int j = it >> 6, c4 = it & 63;
        int r = ((j & 3) << 8) + (sl << 5) + (j >> 2);
        float4 v = __ldg((const float4 *)(W_hh + r * HH) + c4);
        __half2 *dh = (__half2 *)(WHI + j * WSTRIDE + c4 * 4);
        dh[0] = __halves2half2(__float2half_rn(v.x), __float2half_rn(v.y));
        dh[1] = __halves2half2(__float2half_rn(v.z), __float2half_rn(v.w));
    }
    if (tid < 128) {
        int r = ((tid & 3) << 8) + (sl << 5) + (tid >> 2);
        WI[tid]    = W_ih[r];
        BIASS[tid] = b_ih[r] + b_hh[r];
    }
    __syncthreads();

    const int m0 = wm * 16;   // 16-row warp tile
    const uint32_t hhi_u = (uint32_t)__cvta_generic_to_shared(smem_raw + HHI_OFF);
    const uint32_t whi_u = (uint32_t)__cvta_generic_to_shared(WHI);
    // A m16k16 fragment: lanes 0-15 rows m0..15 @k0, lanes 16-31 same rows @k8
    const uint32_t aOff = (uint32_t)((m0 + (lane & 15)) * 528 + ((lane >> 4) * 8) * 2);
    // B j-pair x4: lanes 0-7 (j0,k0), 8-15 (j0,k8), 16-23 (j1,k0), 24-31 (j1,k8)
    const uint32_t bP0 = (uint32_t)((wn * 32 + (lane >> 4) * 8 + (lane & 7)) * 528 +
                                    ((lane >> 3) & 1) * 16);
    const uint32_t bP1 = bP0 + 16 * 528;

    // epilogue mapping (lane-pair exchange): thread owns row rloc, 4 units
    const int p = lane & 1, q = lane >> 2;
    const int rloc = m0 + q + 8 * p;
    int hcol[4];
#pragma unroll
    for (int j = 0; j < 4; j++) hcol[j] = sl * 32 + wn * 8 + 2 * j + ((lane & 3) >> 1);

    float creg[4];
#pragma unroll
    for (int j = 0; j < 4; j++) creg[j] = 0.0f;

    unsigned *barg = g_bar[grp];
    const __half *shh = g_hh + grp * 64 * HH;

    for (int t = 0; t < TT; ++t) {
        // ---- comm-in: h tile via cp.async; x tile (every 32 steps) via LDG+STS ----
        if (t > 0) {
#pragma unroll
            for (int k = 0; k < 4; ++k) {
                int g = k * NTHR + tid;   // 2048 16B chunks
                uint32_t off = (uint32_t)((g >> 5) * 528 + (g & 31) * 16);
                cpasync16(hhi_u + off, shh + g * 8);
            }
            asm volatile("cp.async.commit_group;");
        }
        if ((t & 31) == 0) {
            // 64 rows x 8 float4 chunks = 512; one per thread. 136B stride -> scalar STS.
            int row = tid >> 3, c = tid & 7;
            float4 v = __ldg((const float4 *)(x + (grp * 64 + row) * TT + t) + c);
            float *dst = &XS[row * 34 + c * 4];
            dst[0] = v.x; dst[1] = v.y; dst[2] = v.z; dst[3] = v.w;
        }
        if (t > 0) asm volatile("cp.async.wait_group 0;");
        __syncthreads();   // h tile + x tile visible CTA-wide

        float acc[4][4];
#pragma unroll
        for (int j = 0; j < 4; j++)
#pragma unroll
            for (int e = 0; e < 4; e++) acc[j][e] = 0.0f;

        if (t > 0) {
#pragma unroll
            for (int kk = 0; kk < 16; ++kk) {
                const uint32_t kB = (uint32_t)(kk * 32);
                uint32_t ah[4], bh[4][2];
                ldsm4(hhi_u + aOff + kB, ah[0], ah[1], ah[2], ah[3]);
                ldsm4(whi_u + bP0 + kB, bh[0][0], bh[0][1], bh[1][0], bh[1][1]);
                ldsm4(whi_u + bP1 + kB, bh[2][0], bh[2][1], bh[3][0], bh[3][1]);
#pragma unroll
                for (int j = 0; j < 4; j++)
                    mma_f16(acc[j], ah[0], ah[1], ah[2], ah[3], bh[j][0], bh[j][1]);
            }
        }

        // ---- in-register epilogue ----
        {
            const int ts = t & 31;
            const int grow = grp * 64 + rloc;
            const float xv = XS[rloc * 34 + ts];
#pragma unroll
            for (int j = 0; j < 4; j++) {
                float a0 = acc[j][0], a1 = acc[j][1], a2 = acc[j][2], a3 = acc[j][3];
                float s1 = p ? a0 : a2;
                float r1 = __shfl_xor_sync(0xFFFFFFFFu, s1, 1);
                float s2 = p ? a1 : a3;
                float r2 = __shfl_xor_sync(0xFFFFFFFFu, s2, 1);
                float gi = p ? r1 : a0;
                float gf = p ? r2 : a1;
                float gg = p ? a2 : r1;
                float go = p ? a3 : r2;
                int u4 = (hcol[j] - sl * 32) * 4;
                float4 wi4 = *(const float4 *)&WI[u4];
                float4 bi4 = *(const float4 *)&BIASS[u4];
                gi += xv * wi4.x + bi4.x;
                gf += xv * wi4.y + bi4.y;
                gg += xv * wi4.z + bi4.z;
                go += xv * wi4.w + bi4.w;
                float cc = fsigmoid(gf) * creg[j] + fsigmoid(gi) * ftanh(gg);
                creg[j] = cc;
                float h = fsigmoid(go) * ftanh(cc);
                g_hh[grow * HH + hcol[j]] = __float2half_rn(h);
            }
        }

        // ---- group barrier: tid0 arrive (release), ALL warps acquire-poll ----
        __syncthreads();   // all h-stores of this CTA done before release
        if (tid == 0) {
            if (sl == 0) {
                unsigned *rst = &barg[(t + 448) & 511];
                asm volatile("st.relaxed.gpu.global.u32 [%0],%1;" :: "l"(rst), "r"(0u) : "memory");
            }
            asm volatile("red.release.gpu.global.add.u32 [%0],%1;" :: "l"(&barg[t]), "r"(1u) : "memory");
        }
        if (lane == 0) {
            unsigned v;
            do {
                asm volatile("ld.acquire.gpu.u32 %0,[%1];" : "=r"(v) : "l"(&barg[t]) : "memory");
            } while (v < 8u);
        }
        __syncwarp();
    }

    // ---- fused final projection: warps 0-7 output rows grp*64 + sl*8 + warp ----
    if (warp < 8) {
        int b = grp * 64 + sl * 8 + warp;
        const __half *hh = g_hh + b * HH;
        float s = 0.0f;
#pragma unroll
        for (int k = lane; k < HH; k += 32)
            s += __half2float(__ldcg(&hh[k])) * __ldg(&W_lin[k]);
#pragma unroll
        for (int o = 16; o > 0; o >>= 1) s += __shfl_xor_sync(0xFFFFFFFFu, s, o);
        if (lane == 0) out[b] = s + __ldg(&b_lin[0]);
    }
}

extern "C" void kernel_launch(void *const *d_in, const int *in_sizes, int n_in,
                              void *d_out, int out_size) {
    (void)in_sizes; (void)n_in; (void)out_size;
    const float *x     = (const float *)d_in[0];
    const float *W_ih  = (const float *)d_in[1];
    const float *W_hh  = (const float *)d_in[2];
    const float *b_ih  = (const float *)d_in[3];
    const float *b_hh  = (const float *)d_in[4];
    const float *W_lin = (const float *)d_in[5];
    const float *b_lin = (const float *)d_in[6];
    float *out = (float *)d_out;

    static bool attr_set = false;
    if (!attr_set) {
        cudaFuncSetAttribute(lstm_kernel, cudaFuncAttributeMaxDynamicSharedMemorySize, SMEM_TOTAL);
        attr_set = true;
    }
    lstm_kernel<<<128, NTHR, SMEM_TOTAL>>>(x, W_ih, W_hh, b_ih, b_hh, W_lin, b_lin, out);
}

// round 12
// speedup vs baseline: 3.1793x; 1.0342x over previous
#include <cuda_runtime.h>
#include <cuda_fp16.h>
#include <cstdint>

#define BB 1024
#define TT 512
#define HH 256
#define NTHR 512
#define WSTRIDE 264          // fp16 elems per SMEM row (K=256 + 8 pad) -> 528 B
#define WHI_OFF 0            // 128*528 = 67584
#define HHI_OFF 67584        // 64*528 = 33792
#define WI_OFF  101376       // 128 floats
#define BIAS_OFF 101888      // 128 floats
#define XS_OFF  102400       // 64 rows x 34 floats = 8704 B
#define SMEM_TOTAL 111616

__device__ __half g_hh[BB * HH];
__device__ unsigned g_bar[16][512];   // zero at load; self-cleaning ring

__device__ __forceinline__ void ldsm4(uint32_t a, uint32_t &r0, uint32_t &r1, uint32_t &r2, uint32_t &r3) {
    asm volatile("ldmatrix.sync.aligned.m8n8.x4.shared.b16 {%0,%1,%2,%3},[%4];"
                 : "=r"(r0), "=r"(r1), "=r"(r2), "=r"(r3) : "r"(a));
}
__device__ __forceinline__ void mma_f16(float *c, uint32_t a0, uint32_t a1, uint32_t a2, uint32_t a3,
                                        uint32_t b0, uint32_t b1) {
    asm volatile("mma.sync.aligned.m16n8k16.row.col.f32.f16.f16.f32 "
                 "{%0,%1,%2,%3},{%4,%5,%6,%7},{%8,%9},{%0,%1,%2,%3};"
                 : "+f"(c[0]), "+f"(c[1]), "+f"(c[2]), "+f"(c[3])
                 : "r"(a0), "r"(a1), "r"(a2), "r"(a3), "r"(b0), "r"(b1));
}
__device__ __forceinline__ void cpasync16(uint32_t dst, const void *src) {
    asm volatile("cp.async.cg.shared.global [%0],[%1],16;" :: "r"(dst), "l"(src));
}
// tanh.approx: 1 MUFU op (vs ex2+rcp chains); sigmoid via tanh identity.
__device__ __forceinline__ float ftanha(float x) {
    float y;
    asm("tanh.approx.f32 %0,%1;" : "=f"(y) : "f"(x));
    return y;
}
__device__ __forceinline__ float fsigmoida(float x) {
    return fmaf(ftanha(0.5f * x), 0.5f, 0.5f);
}

extern __shared__ char smem_raw[];

__global__ void __launch_bounds__(NTHR, 1)
lstm_kernel(const float *__restrict__ x, const float *__restrict__ W_ih,
            const float *__restrict__ W_hh, const float *__restrict__ b_ih,
            const float *__restrict__ b_hh, const float *__restrict__ W_lin,
            const float *__restrict__ b_lin, float *__restrict__ out) {
    __half *WHI  = (__half *)(smem_raw + WHI_OFF);
    float *WI    = (float *)(smem_raw + WI_OFF);
    float *BIASS = (float *)(smem_raw + BIAS_OFF);
    float *XS    = (float *)(smem_raw + XS_OFF);

    const int tid  = threadIdx.x;
    const int grp  = blockIdx.x >> 3;   // batch group 0..15 (64 rows)
    const int sl   = blockIdx.x & 7;    // hidden slice 0..7 (32 units)
    const int lane = tid & 31;
    const int warp = tid >> 5;          // 0..15
    const int wm   = warp >> 2, wn = warp & 3;   // 4 x 4 warp grid

    // ---- one-time: W_hh slice (single fp16), unit-interleaved rows j = 4*unit + gate ----
    for (int it = tid; it < 128 * 64; it += NTHR) {
        int j = it >> 6, c4 = it & 63;
        int r = ((j & 3) << 8) + (sl << 5) + (j >> 2);
        float4 v = __ldg((const float4 *)(W_hh + r * HH) + c4);
        __half2 *dh = (__half2 *)(WHI + j * WSTRIDE + c4 * 4);
        dh[0] = __halves2half2(__float2half_rn(v.x), __float2half_rn(v.y));
        dh[1] = __halves2half2(__float2half_rn(v.z), __float2half_rn(v.w));
    }
    if (tid < 128) {
        int r = ((tid & 3) << 8) + (sl << 5) + (tid >> 2);
        WI[tid]    = W_ih[r];
        BIASS[tid] = b_ih[r] + b_hh[r];
    }
    __syncthreads();

    const int m0 = wm * 16;   // 16-row warp tile
    const uint32_t hhi_u = (uint32_t)__cvta_generic_to_shared(smem_raw + HHI_OFF);
    const uint32_t whi_u = (uint32_t)__cvta_generic_to_shared(WHI);
    // A m16k16 fragment: lanes 0-15 rows m0..15 @k0, lanes 16-31 same rows @k8
    const uint32_t aOff = (uint32_t)((m0 + (lane & 15)) * 528 + ((lane >> 4) * 8) * 2);
    // B j-pair x4: lanes 0-7 (j0,k0), 8-15 (j0,k8), 16-23 (j1,k0), 24-31 (j1,k8)
    const uint32_t bP0 = (uint32_t)((wn * 32 + (lane >> 4) * 8 + (lane & 7)) * 528 +
                                    ((lane >> 3) & 1) * 16);
    const uint32_t bP1 = bP0 + 16 * 528;

    // epilogue mapping (lane-pair exchange): thread owns row rloc, 4 units
    const int p = lane & 1, q = lane >> 2;
    const int rloc = m0 + q + 8 * p;
    int hcol[4];
#pragma unroll
    for (int j = 0; j < 4; j++) hcol[j] = sl * 32 + wn * 8 + 2 * j + ((lane & 3) >> 1);

    float creg[4];
#pragma unroll
    for (int j = 0; j < 4; j++) creg[j] = 0.0f;

    unsigned *barg = g_bar[grp];
    const __half *shh = g_hh + grp * 64 * HH;

    for (int t = 0; t < TT; ++t) {
        // ---- comm-in: h tile via cp.async; x tile (every 32 steps) via LDG+STS ----
        if (t > 0) {
#pragma unroll
            for (int k = 0; k < 4; ++k) {
                int g = k * NTHR + tid;   // 2048 16B chunks
                uint32_t off = (uint32_t)((g >> 5) * 528 + (g & 31) * 16);
                cpasync16(hhi_u + off, shh + g * 8);
            }
            asm volatile("cp.async.commit_group;");
        }
        if ((t & 31) == 0) {
            // 64 rows x 8 float4 chunks = 512; one per thread. 136B stride -> scalar STS.
            int row = tid >> 3, c = tid & 7;
            float4 v = __ldg((const float4 *)(x + (grp * 64 + row) * TT + t) + c);
            float *dst = &XS[row * 34 + c * 4];
            dst[0] = v.x; dst[1] = v.y; dst[2] = v.z; dst[3] = v.w;
        }
        if (t > 0) asm volatile("cp.async.wait_group 0;");
        __syncthreads();   // h tile + x tile visible CTA-wide

        float acc[4][4];
#pragma unroll
        for (int j = 0; j < 4; j++)
#pragma unroll
            for (int e = 0; e < 4; e++) acc[j][e] = 0.0f;

        if (t > 0) {
#pragma unroll
            for (int kk = 0; kk < 16; ++kk) {
                const uint32_t kB = (uint32_t)(kk * 32);
                uint32_t ah[4], bh[4][2];
                ldsm4(hhi_u + aOff + kB, ah[0], ah[1], ah[2], ah[3]);
                ldsm4(whi_u + bP0 + kB, bh[0][0], bh[0][1], bh[1][0], bh[1][1]);
                ldsm4(whi_u + bP1 + kB, bh[2][0], bh[2][1], bh[3][0], bh[3][1]);
#pragma unroll
                for (int j = 0; j < 4; j++)
                    mma_f16(acc[j], ah[0], ah[1], ah[2], ah[3], bh[j][0], bh[j][1]);
            }
        }

        // ---- in-register epilogue (tanh.approx activations) ----
        {
            const int ts = t & 31;
            const int grow = grp * 64 + rloc;
            const float xv = XS[rloc * 34 + ts];
#pragma unroll
            for (int j = 0; j < 4; j++) {
                float a0 = acc[j][0], a1 = acc[j][1], a2 = acc[j][2], a3 = acc[j][3];
                float s1 = p ? a0 : a2;
                float r1 = __shfl_xor_sync(0xFFFFFFFFu, s1, 1);
                float s2 = p ? a1 : a3;
                float r2 = __shfl_xor_sync(0xFFFFFFFFu, s2, 1);
                float gi = p ? r1 : a0;
                float gf = p ? r2 : a1;
                float gg = p ? a2 : r1;
                float go = p ? a3 : r2;
                int u4 = (hcol[j] - sl * 32) * 4;
                float4 wi4 = *(const float4 *)&WI[u4];
                float4 bi4 = *(const float4 *)&BIASS[u4];
                gi += xv * wi4.x + bi4.x;
                gf += xv * wi4.y + bi4.y;
                gg += xv * wi4.z + bi4.z;
                go += xv * wi4.w + bi4.w;
                float cc = fsigmoida(gf) * creg[j] + fsigmoida(gi) * ftanha(gg);
                creg[j] = cc;
                float h = fsigmoida(go) * ftanha(cc);
                g_hh[grow * HH + hcol[j]] = __float2half_rn(h);
            }
        }

        // ---- group barrier: tid0 arrive (release), ALL warps acquire-poll ----
        __syncthreads();   // all h-stores of this CTA done before release
        if (tid == 0) {
            if (sl == 0) {
                unsigned *rst = &barg[(t + 448) & 511];
                asm volatile("st.relaxed.gpu.global.u32 [%0],%1;" :: "l"(rst), "r"(0u) : "memory");
            }
            asm volatile("red.release.gpu.global.add.u32 [%0],%1;" :: "l"(&barg[t]), "r"(1u) : "memory");
        }
        if (lane == 0) {
            unsigned v;
            do {
                asm volatile("ld.acquire.gpu.u32 %0,[%1];" : "=r"(v) : "l"(&barg[t]) : "memory");
            } while (v < 8u);
        }
        __syncwarp();
    }

    // ---- fused final projection: warps 0-7 output rows grp*64 + sl*8 + warp ----
    if (warp < 8) {
        int b = grp * 64 + sl * 8 + warp;
        const __half *hh = g_hh + b * HH;
        float s = 0.0f;
#pragma unroll
        for (int k = lane; k < HH; k += 32)
            s += __half2float(__ldcg(&hh[k])) * __ldg(&W_lin[k]);
#pragma unroll
        for (int o = 16; o > 0; o >>= 1) s += __shfl_xor_sync(0xFFFFFFFFu, s, o);
        if (lane == 0) out[b] = s + __ldg(&b_lin[0]);
    }
}

extern "C" void kernel_launch(void *const *d_in, const int *in_sizes, int n_in,
                              void *d_out, int out_size) {
    (void)in_sizes; (void)n_in; (void)out_size;
    const float *x     = (const float *)d_in[0];
    const float *W_ih  = (const float *)d_in[1];
    const float *W_hh  = (const float *)d_in[2];
    const float *b_ih  = (const float *)d_in[3];
    const float *b_hh  = (const float *)d_in[4];
    const float *W_lin = (const float *)d_in[5];
    const float *b_lin = (const float *)d_in[6];
    float *out = (float *)d_out;

    static bool attr_set = false;
    if (!attr_set) {
        cudaFuncSetAttribute(lstm_kernel, cudaFuncAttributeMaxDynamicSharedMemorySize, SMEM_TOTAL);
        attr_set = true;
    }
    lstm_kernel<<<128, NTHR, SMEM_TOTAL>>>(x, W_ih, W_hh, b_ih, b_hh, W_lin, b_lin, out);
}

// round 13
// speedup vs baseline: 3.8258x; 1.2034x over previous
#include <cuda_runtime.h>
#include <cuda_fp16.h>
#include <cstdint>

#define BB 1024
#define TT 512
#define HH 256
#define NTHR 256
#define WSTRIDE 264          // fp16 elems per SMEM row (K=256 + 8 pad) -> 528 B
#define WHI_OFF 0            // 128*528 = 67584
#define HHI_OFF 67584        // 64*528 = 33792
#define WI_OFF  101376       // 128 floats
#define BIAS_OFF 101888      // 128 floats
#define XS_OFF  102400       // 64 rows x 34 floats = 8704 B
#define SMEM_TOTAL 111616

__device__ __half g_hh[BB * HH];
__device__ unsigned g_bar[16][512];   // zero at load; self-cleaning ring

__device__ __forceinline__ void ldsm4(uint32_t a, uint32_t &r0, uint32_t &r1, uint32_t &r2, uint32_t &r3) {
    asm volatile("ldmatrix.sync.aligned.m8n8.x4.shared.b16 {%0,%1,%2,%3},[%4];"
                 : "=r"(r0), "=r"(r1), "=r"(r2), "=r"(r3) : "r"(a));
}
__device__ __forceinline__ void mma_f16(float *c, uint32_t a0, uint32_t a1, uint32_t a2, uint32_t a3,
                                        uint32_t b0, uint32_t b1) {
    asm volatile("mma.sync.aligned.m16n8k16.row.col.f32.f16.f16.f32 "
                 "{%0,%1,%2,%3},{%4,%5,%6,%7},{%8,%9},{%0,%1,%2,%3};"
                 : "+f"(c[0]), "+f"(c[1]), "+f"(c[2]), "+f"(c[3])
                 : "r"(a0), "r"(a1), "r"(a2), "r"(a3), "r"(b0), "r"(b1));
}
__device__ __forceinline__ void cpasync16(uint32_t dst, const void *src) {
    asm volatile("cp.async.cg.shared.global [%0],[%1],16;" :: "r"(dst), "l"(src));
}
__device__ __forceinline__ float ftanha(float x) {
    float y;
    asm("tanh.approx.f32 %0,%1;" : "=f"(y) : "f"(x));
    return y;
}
__device__ __forceinline__ float fsigmoida(float x) {
    return fmaf(ftanha(0.5f * x), 0.5f, 0.5f);
}

extern __shared__ char smem_raw[];

__global__ void __launch_bounds__(NTHR, 1)
lstm_kernel(const float *__restrict__ x, const float *__restrict__ W_ih,
            const float *__restrict__ W_hh, const float *__restrict__ b_ih,
            const float *__restrict__ b_hh, const float *__restrict__ W_lin,
            const float *__restrict__ b_lin, float *__restrict__ out) {
    __half *WHI  = (__half *)(smem_raw + WHI_OFF);
    float *WI    = (float *)(smem_raw + WI_OFF);
    float *BIASS = (float *)(smem_raw + BIAS_OFF);
    float *XS    = (float *)(smem_raw + XS_OFF);

    const int tid  = threadIdx.x;
    const int grp  = blockIdx.x >> 3;   // batch group 0..15 (64 rows)
    const int sl   = blockIdx.x & 7;    // hidden slice 0..7 (32 units)
    const int lane = tid & 31;
    const int warp = tid >> 5;          // 0..7
    const int wm   = warp >> 2, wn = warp & 3;   // 2 x 4 warp grid, m32n32 tiles

    // ---- one-time: W_hh slice (fp16) -> SMEM, unit-interleaved rows j = 4*unit + gate ----
    for (int it = tid; it < 128 * 64; it += NTHR) {
        int j = it >> 6, c4 = it & 63;
        int r = ((j & 3) << 8) + (sl << 5) + (j >> 2);
        float4 v = __ldg((const float4 *)(W_hh + r * HH) + c4);
        __half2 *dh = (__half2 *)(WHI + j * WSTRIDE + c4 * 4);
        dh[0] = __halves2half2(__float2half_rn(v.x), __float2half_rn(v.y));
        dh[1] = __halves2half2(__float2half_rn(v.z), __float2half_rn(v.w));
    }
    if (tid < 128) {
        int r = ((tid & 3) << 8) + (sl << 5) + (tid >> 2);
        WI[tid]    = W_ih[r];
        BIASS[tid] = b_ih[r] + b_hh[r];
    }
    __syncthreads();

    const int m0 = wm * 32;   // 32-row warp tile
    const uint32_t hhi_u = (uint32_t)__cvta_generic_to_shared(smem_raw + HHI_OFF);
    const uint32_t whi_u = (uint32_t)__cvta_generic_to_shared(WHI);
    // A m16k16 fragments: rows m0..m0+15 (aOff0) and +16 (aOff1)
    const uint32_t aOff0 = (uint32_t)((m0 + (lane & 15)) * 528 + ((lane >> 4) * 8) * 2);
    const uint32_t aOff1 = aOff0 + 16 * 528;
    // B j-pair x4: lanes 0-7 (j0,k0), 8-15 (j0,k8), 16-23 (j1,k0), 24-31 (j1,k8)
    const uint32_t bP0 = (uint32_t)((wn * 32 + (lane >> 4) * 8 + (lane & 7)) * 528 +
                                    ((lane >> 3) & 1) * 16);
    const uint32_t bP1 = bP0 + 16 * 528;

    // ---- WEIGHT-STATIONARY: load all B fragments into registers, once ----
    uint32_t breg[16][8];
#pragma unroll
    for (int kk = 0; kk < 16; ++kk) {
        const uint32_t kB = (uint32_t)(kk * 32);
        ldsm4(whi_u + bP0 + kB, breg[kk][0], breg[kk][1], breg[kk][2], breg[kk][3]);
        ldsm4(whi_u + bP1 + kB, breg[kk][4], breg[kk][5], breg[kk][6], breg[kk][7]);
    }

    // epilogue mapping (lane-pair exchange): thread owns rows rloc0, rloc0+16; 4 units
    const int p = lane & 1, q = lane >> 2;
    const int rloc0 = m0 + q + 8 * p;
    int hcol[4];
#pragma unroll
    for (int j = 0; j < 4; j++) hcol[j] = sl * 32 + wn * 8 + 2 * j + ((lane & 3) >> 1);

    float creg[2][4];
#pragma unroll
    for (int i = 0; i < 2; i++)
#pragma unroll
        for (int j = 0; j < 4; j++) creg[i][j] = 0.0f;

    unsigned *barg = g_bar[grp];
    const __half *shh = g_hh + grp * 64 * HH;

    for (int t = 0; t < TT; ++t) {
        // ---- comm-in: h tile via cp.async; x tile (every 32 steps) via LDG+STS ----
        if (t > 0) {
#pragma unroll
            for (int k = 0; k < 8; ++k) {
                int g = k * NTHR + tid;   // 2048 16B chunks
                uint32_t off = (uint32_t)((g >> 5) * 528 + (g & 31) * 16);
                cpasync16(hhi_u + off, shh + g * 8);
            }
            asm volatile("cp.async.commit_group;");
        }
        if ((t & 31) == 0) {
            // 512 float4 chunks; 2 per thread. 136B stride -> scalar STS.
#pragma unroll
            for (int k = 0; k < 2; ++k) {
                int g = k * NTHR + tid;
                int row = g >> 3, c = g & 7;
                float4 v = __ldg((const float4 *)(x + (grp * 64 + row) * TT + t) + c);
                float *dst = &XS[row * 34 + c * 4];
                dst[0] = v.x; dst[1] = v.y; dst[2] = v.z; dst[3] = v.w;
            }
        }
        if (t > 0) asm volatile("cp.async.wait_group 0;");
        __syncthreads();   // h tile + x tile visible CTA-wide

        float acc[2][4][4];
#pragma unroll
        for (int i = 0; i < 2; i++)
#pragma unroll
            for (int j = 0; j < 4; j++)
#pragma unroll
                for (int e = 0; e < 4; e++) acc[i][j][e] = 0.0f;

        if (t > 0) {
#pragma unroll
            for (int kk = 0; kk < 16; ++kk) {
                const uint32_t kB = (uint32_t)(kk * 32);
                uint32_t a0[4], a1[4];
                ldsm4(hhi_u + aOff0 + kB, a0[0], a0[1], a0[2], a0[3]);
                ldsm4(hhi_u + aOff1 + kB, a1[0], a1[1], a1[2], a1[3]);
#pragma unroll
                for (int j = 0; j < 4; j++) {
                    mma_f16(acc[0][j], a0[0], a0[1], a0[2], a0[3],
                            breg[kk][2 * j], breg[kk][2 * j + 1]);
                    mma_f16(acc[1][j], a1[0], a1[1], a1[2], a1[3],
                            breg[kk][2 * j], breg[kk][2 * j + 1]);
                }
            }
        }

        // ---- in-register epilogue (2 row-groups x 4 units) ----
        const int ts = t & 31;
#pragma unroll
        for (int i = 0; i < 2; i++) {
            const int rloc = rloc0 + 16 * i;
            const int grow = grp * 64 + rloc;
            const float xv = XS[rloc * 34 + ts];
#pragma unroll
            for (int j = 0; j < 4; j++) {
                float a0 = acc[i][j][0], a1 = acc[i][j][1], a2 = acc[i][j][2], a3 = acc[i][j][3];
                float s1 = p ? a0 : a2;
                float r1 = __shfl_xor_sync(0xFFFFFFFFu, s1, 1);
                float s2 = p ? a1 : a3;
                float r2 = __shfl_xor_sync(0xFFFFFFFFu, s2, 1);
                float gi = p ? r1 : a0;
                float gf = p ? r2 : a1;
                float gg = p ? a2 : r1;
                float go = p ? a3 : r2;
                int u4 = (hcol[j] - sl * 32) * 4;
                float4 wi4 = *(const float4 *)&WI[u4];
                float4 bi4 = *(const float4 *)&BIASS[u4];
                gi += xv * wi4.x + bi4.x;
                gf += xv * wi4.y + bi4.y;
                gg += xv * wi4.z + bi4.z;
                go += xv * wi4.w + bi4.w;
                float cc = fsigmoida(gf) * creg[i][j] + fsigmoida(gi) * ftanha(gg);
                creg[i][j] = cc;
                float h = fsigmoida(go) * ftanha(cc);
                g_hh[grow * HH + hcol[j]] = __float2half_rn(h);
            }
        }

        // ---- group barrier: tid0 arrive (release), ALL warps acquire-poll ----
        __syncthreads();   // all h-stores of this CTA done before release
        if (tid == 0) {
            if (sl == 0) {
                unsigned *rst = &barg[(t + 448) & 511];
                asm volatile("st.relaxed.gpu.global.u32 [%0],%1;" :: "l"(rst), "r"(0u) : "memory");
            }
            asm volatile("red.release.gpu.global.add.u32 [%0],%1;" :: "l"(&barg[t]), "r"(1u) : "memory");
        }
        if (lane == 0) {
            unsigned v;
            do {
                asm volatile("ld.acquire.gpu.u32 %0,[%1];" : "=r"(v) : "l"(&barg[t]) : "memory");
            } while (v < 8u);
        }
        __syncwarp();
    }

    // ---- fused final projection: warp w outputs row grp*64 + sl*8 + w ----
    {
        int b = grp * 64 + sl * 8 + warp;
        const __half *hh = g_hh + b * HH;
        float s = 0.0f;
#pragma unroll
        for (int k = lane; k < HH; k += 32)
            s += __half2float(__ldcg(&hh[k])) * __ldg(&W_lin[k]);
#pragma unroll
        for (int o = 16; o > 0; o >>= 1) s += __shfl_xor_sync(0xFFFFFFFFu, s, o);
        if (lane == 0) out[b] = s + __ldg(&b_lin[0]);
    }
}

extern "C" void kernel_launch(void *const *d_in, const int *in_sizes, int n_in,
                              void *d_out, int out_size) {
    (void)in_sizes; (void)n_in; (void)out_size;
    const float *x     = (const float *)d_in[0];
    const float *W_ih  = (const float *)d_in[1];
    const float *W_hh  = (const float *)d_in[2];
    const float *b_ih  = (const float *)d_in[3];
    const float *b_hh  = (const float *)d_in[4];
    const float *W_lin = (const float *)d_in[5];
    const float *b_lin = (const float *)d_in[6];
    float *out = (float *)d_out;

    static bool attr_set = false;
    if (!attr_set) {
        cudaFuncSetAttribute(lstm_kernel, cudaFuncAttributeMaxDynamicSharedMemorySize, SMEM_TOTAL);
        attr_set = true;
    }
    lstm_kernel<<<128, NTHR, SMEM_TOTAL>>>(x, W_ih, W_hh, b_ih, b_hh, W_lin, b_lin, out);
}

// round 14
// speedup vs baseline: 4.0346x; 1.0546x over previous
#include <cuda_runtime.h>
#include <cuda_fp16.h>
#include <cstdint>

#define BB 1024
#define TT 512
#define HH 256
#define NTHR 256
#define WSTRIDE 264          // fp16 elems per SMEM row (K=256 + 8 pad) -> 528 B
#define WHI_OFF 0            // 128*528 = 67584
#define HHI_OFF 67584        // 64*528 = 33792
#define WI_OFF  101376       // 128 floats
#define BIAS_OFF 101888      // 128 floats
#define XS_OFF  102400       // 64 rows x 34 floats = 8704 B
#define SMEM_TOTAL 111616

__device__ __half g_hh[BB * HH];
__device__ unsigned g_bar[16][2][512];   // [group][cohort][t]; zero at load; self-cleaning ring

#define COHORT_BAR(c) asm volatile("bar.sync %0, 128;" :: "r"(1 + (c)) : "memory")

__device__ __forceinline__ void ldsm4(uint32_t a, uint32_t &r0, uint32_t &r1, uint32_t &r2, uint32_t &r3) {
    asm volatile("ldmatrix.sync.aligned.m8n8.x4.shared.b16 {%0,%1,%2,%3},[%4];"
                 : "=r"(r0), "=r"(r1), "=r"(r2), "=r"(r3) : "r"(a));
}
__device__ __forceinline__ void mma_f16(float *c, uint32_t a0, uint32_t a1, uint32_t a2, uint32_t a3,
                                        uint32_t b0, uint32_t b1) {
    asm volatile("mma.sync.aligned.m16n8k16.row.col.f32.f16.f16.f32 "
                 "{%0,%1,%2,%3},{%4,%5,%6,%7},{%8,%9},{%0,%1,%2,%3};"
                 : "+f"(c[0]), "+f"(c[1]), "+f"(c[2]), "+f"(c[3])
                 : "r"(a0), "r"(a1), "r"(a2), "r"(a3), "r"(b0), "r"(b1));
}
__device__ __forceinline__ void cpasync16(uint32_t dst, const void *src) {
    asm volatile("cp.async.cg.shared.global [%0],[%1],16;" :: "r"(dst), "l"(src));
}
__device__ __forceinline__ float ftanha(float x) {
    float y;
    asm("tanh.approx.f32 %0,%1;" : "=f"(y) : "f"(x));
    return y;
}
__device__ __forceinline__ float fsigmoida(float x) {
    return fmaf(ftanha(0.5f * x), 0.5f, 0.5f);
}

extern __shared__ char smem_raw[];

__global__ void __launch_bounds__(NTHR, 1)
lstm_kernel(const float *__restrict__ x, const float *__restrict__ W_ih,
            const float *__restrict__ W_hh, const float *__restrict__ b_ih,
            const float *__restrict__ b_hh, const float *__restrict__ W_lin,
            const float *__restrict__ b_lin, float *__restrict__ out) {
    __half *WHI  = (__half *)(smem_raw + WHI_OFF);
    float *WI    = (float *)(smem_raw + WI_OFF);
    float *BIASS = (float *)(smem_raw + BIAS_OFF);
    float *XS    = (float *)(smem_raw + XS_OFF);

    const int tid  = threadIdx.x;
    const int grp  = blockIdx.x >> 3;   // batch group 0..15 (64 rows)
    const int sl   = blockIdx.x & 7;    // hidden slice 0..7 (32 units)
    const int lane = tid & 31;
    const int warp = tid >> 5;          // 0..7
    const int coh  = warp >> 2;         // cohort 0: batch rows 0-31, cohort 1: rows 32-63
    const int wn   = warp & 3;          // n-position within cohort
    const int ct   = tid & 127;         // cohort-local tid

    // ---- one-time: W_hh slice (fp16) -> SMEM, unit-interleaved rows j = 4*unit + gate ----
    for (int it = tid; it < 128 * 64; it += NTHR) {
        int j = it >> 6, c4 = it & 63;
        int r = ((j & 3) << 8) + (sl << 5) + (j >> 2);
        float4 v = __ldg((const float4 *)(W_hh + r * HH) + c4);
        __half2 *dh = (__half2 *)(WHI + j * WSTRIDE + c4 * 4);
        dh[0] = __halves2half2(__float2half_rn(v.x), __float2half_rn(v.y));
        dh[1] = __halves2half2(__float2half_rn(v.z), __float2half_rn(v.w));
    }
    if (tid < 128) {
        int r = ((tid & 3) << 8) + (sl << 5) + (tid >> 2);
        WI[tid]    = W_ih[r];
        BIASS[tid] = b_ih[r] + b_hh[r];
    }
    __syncthreads();

    const int m0 = coh * 32;   // cohort's 32-row batch tile
    const uint32_t hhi_u = (uint32_t)__cvta_generic_to_shared(smem_raw + HHI_OFF);
    const uint32_t whi_u = (uint32_t)__cvta_generic_to_shared(WHI);
    // A m16k16 fragments: rows m0..m0+15 (aOff0) and +16 (aOff1)
    const uint32_t aOff0 = (uint32_t)((m0 + (lane & 15)) * 528 + ((lane >> 4) * 8) * 2);
    const uint32_t aOff1 = aOff0 + 16 * 528;
    // B j-pair x4: lanes 0-7 (j0,k0), 8-15 (j0,k8), 16-23 (j1,k0), 24-31 (j1,k8)
    const uint32_t bP0 = (uint32_t)((wn * 32 + (lane >> 4) * 8 + (lane & 7)) * 528 +
                                    ((lane >> 3) & 1) * 16);
    const uint32_t bP1 = bP0 + 16 * 528;

    // ---- WEIGHT-STATIONARY: load all B fragments into registers, once ----
    uint32_t breg[16][8];
#pragma unroll
    for (int kk = 0; kk < 16; ++kk) {
        const uint32_t kB = (uint32_t)(kk * 32);
        ldsm4(whi_u + bP0 + kB, breg[kk][0], breg[kk][1], breg[kk][2], breg[kk][3]);
        ldsm4(whi_u + bP1 + kB, breg[kk][4], breg[kk][5], breg[kk][6], breg[kk][7]);
    }

    // epilogue mapping (lane-pair exchange): thread owns rows rloc0, rloc0+16; 4 units
    const int p = lane & 1, q = lane >> 2;
    const int rloc0 = m0 + q + 8 * p;
    int hcol[4];
#pragma unroll
    for (int j = 0; j < 4; j++) hcol[j] = sl * 32 + wn * 8 + 2 * j + ((lane & 3) >> 1);

    float creg[2][4];
#pragma unroll
    for (int i = 0; i < 2; i++)
#pragma unroll
        for (int j = 0; j < 4; j++) creg[i][j] = 0.0f;

    unsigned *barg = g_bar[grp][coh];
    const __half *shh = g_hh + (grp * 64 + m0) * HH;   // cohort's 32 rows

    for (int t = 0; t < TT; ++t) {
        // ---- comm-in (per cohort): 32-row h tile via cp.async; x tile every 32 steps ----
        if (t > 0) {
#pragma unroll
            for (int k = 0; k < 8; ++k) {
                int g = k * 128 + ct;     // 1024 16B chunks (32 rows x 32 chunks)
                uint32_t off = (uint32_t)((m0 + (g >> 5)) * 528 + (g & 31) * 16);
                cpasync16(hhi_u + off, shh + g * 8);
            }
            asm volatile("cp.async.commit_group;");
        }
        if ((t & 31) == 0) {
            // 32 rows x 8 float4 chunks = 256; 2 per cohort thread. 136B stride -> scalar STS.
#pragma unroll
            for (int k = 0; k < 2; ++k) {
                int g = k * 128 + ct;
                int row = m0 + (g >> 3), c8 = g & 7;
                float4 v = __ldg((const float4 *)(x + (grp * 64 + row) * TT + t) + c8);
                float *dst = &XS[row * 34 + c8 * 4];
                dst[0] = v.x; dst[1] = v.y; dst[2] = v.z; dst[3] = v.w;
            }
        }
        if (t > 0) asm volatile("cp.async.wait_group 0;");
        COHORT_BAR(coh);   // cohort's h tile + x tile visible to cohort

        float acc[2][4][4];
#pragma unroll
        for (int i = 0; i < 2; i++)
#pragma unroll
            for (int j = 0; j < 4; j++)
#pragma unroll
                for (int e = 0; e < 4; e++) acc[i][j][e] = 0.0f;

        if (t > 0) {
#pragma unroll
            for (int kk = 0; kk < 16; ++kk) {
                const uint32_t kB = (uint32_t)(kk * 32);
                uint32_t a0[4], a1[4];
                ldsm4(hhi_u + aOff0 + kB, a0[0], a0[1], a0[2], a0[3]);
                ldsm4(hhi_u + aOff1 + kB, a1[0], a1[1], a1[2], a1[3]);
#pragma unroll
                for (int j = 0; j < 4; j++) {
                    mma_f16(acc[0][j], a0[0], a0[1], a0[2], a0[3],
                            breg[kk][2 * j], breg[kk][2 * j + 1]);
                    mma_f16(acc[1][j], a1[0], a1[1], a1[2], a1[3],
                            breg[kk][2 * j], breg[kk][2 * j + 1]);
                }
            }
        }

        // ---- in-register epilogue (2 row-groups x 4 units) ----
        const int ts = t & 31;
#pragma unroll
        for (int i = 0; i < 2; i++) {
            const int rloc = rloc0 + 16 * i;
            const int grow = grp * 64 + rloc;
            const float xv = XS[rloc * 34 + ts];
#pragma unroll
            for (int j = 0; j < 4; j++) {
                float a0 = acc[i][j][0], a1 = acc[i][j][1], a2 = acc[i][j][2], a3 = acc[i][j][3];
                float s1 = p ? a0 : a2;
                float r1 = __shfl_xor_sync(0xFFFFFFFFu, s1, 1);
                float s2 = p ? a1 : a3;
                float r2 = __shfl_xor_sync(0xFFFFFFFFu, s2, 1);
                float gi = p ? r1 : a0;
                float gf = p ? r2 : a1;
                float gg = p ? a2 : r1;
                float go = p ? a3 : r2;
                int u4 = (hcol[j] - sl * 32) * 4;
                float4 wi4 = *(const float4 *)&WI[u4];
                float4 bi4 = *(const float4 *)&BIASS[u4];
                gi += xv * wi4.x + bi4.x;
                gf += xv * wi4.y + bi4.y;
                gg += xv * wi4.z + bi4.z;
                go += xv * wi4.w + bi4.w;
                float cc = fsigmoida(gf) * creg[i][j] + fsigmoida(gi) * ftanha(gg);
                creg[i][j] = cc;
                float h = fsigmoida(go) * ftanha(cc);
                g_hh[grow * HH + hcol[j]] = __float2half_rn(h);
            }
        }

        // ---- per-cohort group barrier: ct0 arrive (release), all cohort warps poll ----
        COHORT_BAR(coh);   // cohort's h stores done before release
        if (ct == 0) {
            if (sl == 0) {
                unsigned *rst = &barg[(t + 448) & 511];
                asm volatile("st.relaxed.gpu.global.u32 [%0],%1;" :: "l"(rst), "r"(0u) : "memory");
            }
            asm volatile("red.release.gpu.global.add.u32 [%0],%1;" :: "l"(&barg[t]), "r"(1u) : "memory");
        }
        if (lane == 0) {
            unsigned v;
            do {
                asm volatile("ld.acquire.gpu.u32 %0,[%1];" : "=r"(v) : "l"(&barg[t]) : "memory");
            } while (v < 8u);
        }
        __syncwarp();
    }

    // ---- fused final projection: warp reads a row its own cohort produced group-wide ----
    {
        int b = grp * 64 + coh * 32 + sl * 4 + (warp & 3);
        const __half *hh = g_hh + b * HH;
        float s = 0.0f;
#pragma unroll
        for (int k = lane; k < HH; k += 32)
            s += __half2float(__ldcg(&hh[k])) * __ldg(&W_lin[k]);
#pragma unroll
        for (int o = 16; o > 0; o >>= 1) s += __shfl_xor_sync(0xFFFFFFFFu, s, o);
        if (lane == 0) out[b] = s + __ldg(&b_lin[0]);
    }
}

extern "C" void kernel_launch(void *const *d_in, const int *in_sizes, int n_in,
                              void *d_out, int out_size) {
    (void)in_sizes; (void)n_in; (void)out_size;
    const float *x     = (const float *)d_in[0];
    const float *W_ih  = (const float *)d_in[1];
    const float *W_hh  = (const float *)d_in[2];
    const float *b_ih  = (const float *)d_in[3];
    const float *b_hh  = (const float *)d_in[4];
    const float *W_lin = (const float *)d_in[5];
    const float *b_lin = (const float *)d_in[6];
    float *out = (float *)d_out;

    static bool attr_set = false;
    if (!attr_set) {
        cudaFuncSetAttribute(lstm_kernel, cudaFuncAttributeMaxDynamicSharedMemorySize, SMEM_TOTAL);
        attr_set = true;
    }
    lstm_kernel<<<128, NTHR, SMEM_TOTAL>>>(x, W_ih, W_hh, b_ih, b_hh, W_lin, b_lin, out);
}

// round 15
// speedup vs baseline: 4.4973x; 1.1147x over previous
#include <cuda_runtime.h>
#include <cuda_fp16.h>
#include <cstdint>

#define BB 1024
#define TT 512
#define HH 256
#define NTHR 256
#define WSTRIDE 264          // fp16 elems per SMEM row (K=256 + 8 pad) -> 528 B
#define WHI_OFF 0            // 128*528 = 67584
#define HHI_OFF 67584        // 64*528 = 33792
#define WI_OFF  101376       // 128 floats
#define BIAS_OFF 101888      // 128 floats
#define XS_OFF  102400       // 64 rows x 34 floats = 8704 B
#define HOUT_OFF 111104      // 64 rows x 40 halves = 5120 B (80B row stride, 16-aligned)
#define SMEM_TOTAL 116224

__device__ __half g_hh[BB * HH];
__device__ unsigned g_bar[16][2][512];   // [group][cohort][t]; zero at load; self-cleaning ring

#define COHORT_BAR(c) asm volatile("bar.sync %0, 128;" :: "r"(1 + (c)) : "memory")

__device__ __forceinline__ void ldsm4(uint32_t a, uint32_t &r0, uint32_t &r1, uint32_t &r2, uint32_t &r3) {
    asm volatile("ldmatrix.sync.aligned.m8n8.x4.shared.b16 {%0,%1,%2,%3},[%4];"
                 : "=r"(r0), "=r"(r1), "=r"(r2), "=r"(r3) : "r"(a));
}
__device__ __forceinline__ void mma_f16(float *c, uint32_t a0, uint32_t a1, uint32_t a2, uint32_t a3,
                                        uint32_t b0, uint32_t b1) {
    asm volatile("mma.sync.aligned.m16n8k16.row.col.f32.f16.f16.f32 "
                 "{%0,%1,%2,%3},{%4,%5,%6,%7},{%8,%9},{%0,%1,%2,%3};"
                 : "+f"(c[0]), "+f"(c[1]), "+f"(c[2]), "+f"(c[3])
                 : "r"(a0), "r"(a1), "r"(a2), "r"(a3), "r"(b0), "r"(b1));
}
__device__ __forceinline__ void cpasync16(uint32_t dst, const void *src) {
    asm volatile("cp.async.cg.shared.global [%0],[%1],16;" :: "r"(dst), "l"(src));
}
__device__ __forceinline__ float ftanha(float x) {
    float y;
    asm("tanh.approx.f32 %0,%1;" : "=f"(y) : "f"(x));
    return y;
}
__device__ __forceinline__ float fsigmoida(float x) {
    return fmaf(ftanha(0.5f * x), 0.5f, 0.5f);
}

extern __shared__ char smem_raw[];

__global__ void __launch_bounds__(NTHR, 1)
lstm_kernel(const float *__restrict__ x, const float *__restrict__ W_ih,
            const float *__restrict__ W_hh, const float *__restrict__ b_ih,
            const float *__restrict__ b_hh, const float *__restrict__ W_lin,
            const float *__restrict__ b_lin, float *__restrict__ out) {
    __half *WHI  = (__half *)(smem_raw + WHI_OFF);
    float *WI    = (float *)(smem_raw + WI_OFF);
    float *BIASS = (float *)(smem_raw + BIAS_OFF);
    float *XS    = (float *)(smem_raw + XS_OFF);
    __half *HOUT = (__half *)(smem_raw + HOUT_OFF);

    const int tid  = threadIdx.x;
    const int grp  = blockIdx.x >> 3;   // batch group 0..15 (64 rows)
    const int sl   = blockIdx.x & 7;    // hidden slice 0..7 (32 units)
    const int lane = tid & 31;
    const int warp = tid >> 5;          // 0..7
    const int coh  = warp >> 2;         // cohort 0: batch rows 0-31, cohort 1: rows 32-63
    const int wn   = warp & 3;          // n-position within cohort
    const int ct   = tid & 127;         // cohort-local tid

    // ---- one-time: W_hh slice (fp16) -> SMEM, unit-interleaved rows j = 4*unit + gate ----
    for (int it = tid; it < 128 * 64; it += NTHR) {
        int j = it >> 6, c4 = it & 63;
        int r = ((j & 3) << 8) + (sl << 5) + (j >> 2);
        float4 v = __ldg((const float4 *)(W_hh + r * HH) + c4);
        __half2 *dh = (__half2 *)(WHI + j * WSTRIDE + c4 * 4);
        dh[0] = __halves2half2(__float2half_rn(v.x), __float2half_rn(v.y));
        dh[1] = __halves2half2(__float2half_rn(v.z), __float2half_rn(v.w));
    }
    if (tid < 128) {
        int r = ((tid & 3) << 8) + (sl << 5) + (tid >> 2);
        WI[tid]    = W_ih[r];
        BIASS[tid] = b_ih[r] + b_hh[r];
    }
    __syncthreads();

    const int m0 = coh * 32;   // cohort's 32-row batch tile
    const uint32_t hhi_u = (uint32_t)__cvta_generic_to_shared(smem_raw + HHI_OFF);
    const uint32_t whi_u = (uint32_t)__cvta_generic_to_shared(WHI);
    // A m16k16 fragments: rows m0..m0+15 (aOff0) and +16 (aOff1)
    const uint32_t aOff0 = (uint32_t)((m0 + (lane & 15)) * 528 + ((lane >> 4) * 8) * 2);
    const uint32_t aOff1 = aOff0 + 16 * 528;
    // B j-pair x4: lanes 0-7 (j0,k0), 8-15 (j0,k8), 16-23 (j1,k0), 24-31 (j1,k8)
    const uint32_t bP0 = (uint32_t)((wn * 32 + (lane >> 4) * 8 + (lane & 7)) * 528 +
                                    ((lane >> 3) & 1) * 16);
    const uint32_t bP1 = bP0 + 16 * 528;

    // ---- WEIGHT-STATIONARY: load all B fragments into registers, once ----
    uint32_t breg[16][8];
#pragma unroll
    for (int kk = 0; kk < 16; ++kk) {
        const uint32_t kB = (uint32_t)(kk * 32);
        ldsm4(whi_u + bP0 + kB, breg[kk][0], breg[kk][1], breg[kk][2], breg[kk][3]);
        ldsm4(whi_u + bP1 + kB, breg[kk][4], breg[kk][5], breg[kk][6], breg[kk][7]);
    }

    // epilogue mapping (lane-pair exchange): thread owns rows rloc0, rloc0+16; 4 units
    const int p = lane & 1, q = lane >> 2;
    const int rloc0 = m0 + q + 8 * p;
    int ucol[4];   // CTA-local unit index 0..31
#pragma unroll
    for (int j = 0; j < 4; j++) ucol[j] = wn * 8 + 2 * j + ((lane & 3) >> 1);

    float creg[2][4];
#pragma unroll
    for (int i = 0; i < 2; i++)
#pragma unroll
        for (int j = 0; j < 4; j++) creg[i][j] = 0.0f;

    unsigned *barg = g_bar[grp][coh];
    const __half *shh = g_hh + (grp * 64 + m0) * HH;   // cohort's 32 rows

    for (int t = 0; t < TT; ++t) {
        // ---- comm-in (per cohort): 32-row h tile via cp.async; x tile every 32 steps ----
        if (t > 0) {
#pragma unroll
            for (int k = 0; k < 8; ++k) {
                int g = k * 128 + ct;     // 1024 16B chunks (32 rows x 32 chunks)
                uint32_t off = (uint32_t)((m0 + (g >> 5)) * 528 + (g & 31) * 16);
                cpasync16(hhi_u + off, shh + g * 8);
            }
            asm volatile("cp.async.commit_group;");
        }
        if ((t & 31) == 0) {
            // 32 rows x 8 float4 chunks = 256; 2 per cohort thread. 136B stride -> scalar STS.
#pragma unroll
            for (int k = 0; k < 2; ++k) {
                int g = k * 128 + ct;
                int row = m0 + (g >> 3), c8 = g & 7;
                float4 v = __ldg((const float4 *)(x + (grp * 64 + row) * TT + t) + c8);
                float *dst = &XS[row * 34 + c8 * 4];
                dst[0] = v.x; dst[1] = v.y; dst[2] = v.z; dst[3] = v.w;
            }
        }
        if (t > 0) asm volatile("cp.async.wait_group 0;");
        COHORT_BAR(coh);   // cohort's h tile + x tile visible to cohort

        float acc[2][4][4];
#pragma unroll
        for (int i = 0; i < 2; i++)
#pragma unroll
            for (int j = 0; j < 4; j++)
#pragma unroll
                for (int e = 0; e < 4; e++) acc[i][j][e] = 0.0f;

        if (t > 0) {
#pragma unroll
            for (int kk = 0; kk < 16; ++kk) {
                const uint32_t kB = (uint32_t)(kk * 32);
                uint32_t a0[4], a1[4];
                ldsm4(hhi_u + aOff0 + kB, a0[0], a0[1], a0[2], a0[3]);
                ldsm4(hhi_u + aOff1 + kB, a1[0], a1[1], a1[2], a1[3]);
#pragma unroll
                for (int j = 0; j < 4; j++) {
                    mma_f16(acc[0][j], a0[0], a0[1], a0[2], a0[3],
                            breg[kk][2 * j], breg[kk][2 * j + 1]);
                    mma_f16(acc[1][j], a1[0], a1[1], a1[2], a1[3],
                            breg[kk][2 * j], breg[kk][2 * j + 1]);
                }
            }
        }

        // ---- in-register epilogue (2 row-groups x 4 units) -> HOUT SMEM staging ----
        const int ts = t & 31;
#pragma unroll
        for (int i = 0; i < 2; i++) {
            const int rloc = rloc0 + 16 * i;
            const float xv = XS[rloc * 34 + ts];
#pragma unroll
            for (int j = 0; j < 4; j++) {
                float a0 = acc[i][j][0], a1 = acc[i][j][1], a2 = acc[i][j][2], a3 = acc[i][j][3];
                float s1 = p ? a0 : a2;
                float r1 = __shfl_xor_sync(0xFFFFFFFFu, s1, 1);
                float s2 = p ? a1 : a3;
                float r2 = __shfl_xor_sync(0xFFFFFFFFu, s2, 1);
                float gi = p ? r1 : a0;
                float gf = p ? r2 : a1;
                float gg = p ? a2 : r1;
                float go = p ? a3 : r2;
                int u4 = ucol[j] * 4;
                float4 wi4 = *(const float4 *)&WI[u4];
                float4 bi4 = *(const float4 *)&BIASS[u4];
                gi += xv * wi4.x + bi4.x;
                gf += xv * wi4.y + bi4.y;
                gg += xv * wi4.z + bi4.z;
                go += xv * wi4.w + bi4.w;
                float cc = fsigmoida(gf) * creg[i][j] + fsigmoida(gi) * ftanha(gg);
                creg[i][j] = cc;
                float h = fsigmoida(go) * ftanha(cc);
                HOUT[rloc * 40 + ucol[j]] = __float2half_rn(h);
            }
        }

        // ---- coalesced writeback: HOUT -> g_hh, one 16B STG per cohort thread ----
        COHORT_BAR(coh);   // HOUT staging visible within cohort
        {
            int row = m0 + (ct >> 2), c16 = ct & 3;
            uint4 v = *(const uint4 *)&HOUT[row * 40 + c16 * 8];
            *(uint4 *)&g_hh[(grp * 64 + row) * HH + sl * 32 + c16 * 8] = v;
        }

        // ---- per-cohort group barrier: ct0 arrive (release), all cohort warps poll ----
        COHORT_BAR(coh);   // cohort's h STGs issued before release
        if (ct == 0) {
            if (sl == 0) {
                unsigned *rst = &barg[(t + 448) & 511];
                asm volatile("st.relaxed.gpu.global.u32 [%0],%1;" :: "l"(rst), "r"(0u) : "memory");
            }
            asm volatile("red.release.gpu.global.add.u32 [%0],%1;" :: "l"(&barg[t]), "r"(1u) : "memory");
        }
        if (lane == 0) {
            unsigned v;
            do {
                asm volatile("ld.acquire.gpu.u32 %0,[%1];" : "=r"(v) : "l"(&barg[t]) : "memory");
            } while (v < 8u);
        }
        __syncwarp();
    }

    // ---- fused final projection: warp reads a row its own cohort produced group-wide ----
    {
        int b = grp * 64 + coh * 32 + sl * 4 + (warp & 3);
        const __half *hh = g_hh + b * HH;
        float s = 0.0f;
#pragma unroll
        for (int k = lane; k < HH; k += 32)
            s += __half2float(__ldcg(&hh[k])) * __ldg(&W_lin[k]);
#pragma unroll
        for (int o = 16; o > 0; o >>= 1) s += __shfl_xor_sync(0xFFFFFFFFu, s, o);
        if (lane == 0) out[b] = s + __ldg(&b_lin[0]);
    }
}

extern "C" void kernel_launch(void *const *d_in, const int *in_sizes, int n_in,
                              void *d_out, int out_size) {
    (void)in_sizes; (void)n_in; (void)out_size;
    const float *x     = (const float *)d_in[0];
    const float *W_ih  = (const float *)d_in[1];
    const float *W_hh  = (const float *)d_in[2];
    const float *b_ih  = (const float *)d_in[3];
    const float *b_hh  = (const float *)d_in[4];
    const float *W_lin = (const float *)d_in[5];
    const float *b_lin = (const float *)d_in[6];
    float *out = (float *)d_out;

    static bool attr_set = false;
    if (!attr_set) {
        cudaFuncSetAttribute(lstm_kernel, cudaFuncAttributeMaxDynamicSharedMemorySize, SMEM_TOTAL);
        attr_set = true;
    }
    lstm_kernel<<<128, NTHR, SMEM_TOTAL>>>(x, W_ih, W_hh, b_ih, b_hh, W_lin, b_lin, out);
}